// round 7
// baseline (speedup 1.0000x reference)
#include <cuda_runtime.h>
#include <cuda_bf16.h>
#include <cstdint>

#define T_ 64
#define B_ 8
#define S_ 512
#define H_ 512
#define TBH (T_*B_*H_)
#define BSH (B_*S_*H_)

// ---------------- scratch (no device allocations allowed) ----------------
__device__ float g_enc[BSH];                 // tanh(enc + cov*wcov), [B,S,H]
__device__ __nv_bfloat16 g_encH[BSH];        // bf16 hi/lo split of g_enc
__device__ __nv_bfloat16 g_encL[BSH];
__device__ __nv_bfloat16 g_decH[TBH];
__device__ __nv_bfloat16 g_decL[TBH];
__device__ __nv_bfloat16 g_WcTH[H_*H_];      // Wc^T hi/lo, [n][k]
__device__ __nv_bfloat16 g_WcTL[H_*H_];
__device__ __nv_bfloat16 g_WqTH[H_*H_];
__device__ __nv_bfloat16 g_WqTL[H_*H_];
__device__ float g_a1 [TBH];                 // dec@Wq + bq, rows r=t*B+b
__device__ float g_a2 [BSH];                 // enc'@Wc, rows b*S+s
__device__ float g_cp [4][TBH];              // c split-K partials
__device__ float g_op [4][TBH];              // out split-K partials

// ---------------- math helpers ----------------
__device__ __forceinline__ float ex2f_(float x){ float y; asm("ex2.approx.f32 %0, %1;" : "=f"(y) : "f"(x)); return y; }
__device__ __forceinline__ float rcpf_(float x){ float y; asm("rcp.approx.f32 %0, %1;" : "=f"(y) : "f"(x)); return y; }
__device__ __forceinline__ float tanhf_hw(float x){ float y; asm("tanh.approx.f32 %0, %1;" : "=f"(y) : "f"(x)); return y; }

__device__ __forceinline__ float fast_tanh(float x){
    x = fminf(fmaxf(x, -15.0f), 15.0f);
    float e = ex2f_(x * 2.8853900817779268f);
    return (e - 1.0f) * rcpf_(e + 1.0f);
}

__device__ __forceinline__ void ffma2(uint64_t& d, uint64_t a, uint64_t b){
    asm("fma.rn.f32x2 %0, %1, %2, %0;" : "+l"(d) : "l"(a), "l"(b));
}
__device__ __forceinline__ uint64_t pk2dup(float a){
    uint64_t r; asm("mov.b64 %0, {%1, %1};" : "=l"(r) : "f"(a)); return r;
}
__device__ __forceinline__ float2 upk2(uint64_t p){
    float2 f; asm("mov.b64 {%0, %1}, %2;" : "=f"(f.x), "=f"(f.y) : "l"(p)); return f;
}

__device__ __forceinline__ void split_bf16(float x, __nv_bfloat16& h, __nv_bfloat16& l){
    h = __float2bfloat16(x);
    l = __float2bfloat16(x - __bfloat162float(h));
}

__device__ __forceinline__ uint32_t smem_to_u32(const void* p){
    uint32_t a;
    asm("{ .reg .u64 t; cvta.to.shared.u64 t, %1; cvt.u32.u64 %0, t; }" : "=r"(a) : "l"(p));
    return a;
}

#define LDSM4(r, addr) \
    asm volatile("ldmatrix.sync.aligned.m8n8.x4.shared.b16 {%0,%1,%2,%3}, [%4];" \
        : "=r"((r)[0]), "=r"((r)[1]), "=r"((r)[2]), "=r"((r)[3]) : "r"(addr))

#define MMA_BF16(d, a, b0v, b1v) \
    asm volatile("mma.sync.aligned.m16n8k16.row.col.f32.bf16.bf16.f32 " \
        "{%0,%1,%2,%3}, {%4,%5,%6,%7}, {%8,%9}, {%0,%1,%2,%3};" \
        : "+f"((d)[0]), "+f"((d)[1]), "+f"((d)[2]), "+f"((d)[3]) \
        : "r"((a)[0]), "r"((a)[1]), "r"((a)[2]), "r"((a)[3]), "r"(b0v), "r"(b1v))

// -------- enc' = tanh(enc + cov*wcov) + bf16 hi/lo split --------
__global__ void prep_enc_kernel(const float* __restrict__ enc,
                                const float* __restrict__ cov,
                                const float* __restrict__ wcov)
{
    int idx = blockIdx.x * 256 + threadIdx.x;
    int h  = idx & (H_-1);
    int bs = idx >> 9;
    int s  = bs & (S_-1);
    int b  = bs >> 9;
    float e = enc[(s*B_ + b)*H_ + h];
    float t = fast_tanh(fmaf(cov[b*S_ + s], wcov[h], e));
    g_enc[idx] = t;
    __nv_bfloat16 hh, ll; split_bf16(t, hh, ll);
    g_encH[idx] = hh; g_encL[idx] = ll;
}

__global__ void split_dec_kernel(const float* __restrict__ dec)
{
    int idx = blockIdx.x * 256 + threadIdx.x;
    __nv_bfloat16 hh, ll; split_bf16(dec[idx], hh, ll);
    g_decH[idx] = hh; g_decL[idx] = ll;
}

// transpose + split Wq (z=0) / Wc (z=1): W[k][n] -> WT hi/lo [n][k]
__global__ void transW_kernel(const float* __restrict__ Wq, const float* __restrict__ Wc)
{
    const float* W = blockIdx.z ? Wc : Wq;
    __nv_bfloat16* THp = blockIdx.z ? g_WcTH : g_WqTH;
    __nv_bfloat16* TLp = blockIdx.z ? g_WcTL : g_WqTL;
    __shared__ float tile[32][33];
    int x = blockIdx.x*32 + threadIdx.x;     // n
    int y0 = blockIdx.y*32;                  // k base
    #pragma unroll
    for (int i = 0; i < 4; i++)
        tile[threadIdx.y + i*8][threadIdx.x] = W[(long)(y0 + threadIdx.y + i*8)*H_ + x];
    __syncthreads();
    int xo = y0 + threadIdx.x;               // k
    int yo = blockIdx.x*32;                  // n base
    #pragma unroll
    for (int i = 0; i < 4; i++) {
        float vv = tile[threadIdx.x][threadIdx.y + i*8];
        __nv_bfloat16 hh, ll; split_bf16(vv, hh, ll);
        long o = (long)(yo + threadIdx.y + i*8)*H_ + xo;
        THp[o] = hh; TLp[o] = ll;
    }
}

// -------- HMMA qc GEMM: 128x128 per CTA, K=512, 3-term bf16 split --------
// blocks 0..127: a2 = enc'@Wc ; blocks 128..143: a1 = dec@Wq + bq
#define QC_PAD 40                            // 32 + 8 pad (conflict-free ldmatrix)
#define QC_AELEMS (2*2*128*QC_PAD)           // 20480 bf16
#define QC_SMEM_BYTES (2*QC_AELEMS*2)        // 81920 B

__global__ __launch_bounds__(256)
void qc_hmma_kernel(const float* __restrict__ bq)
{
    extern __shared__ __nv_bfloat16 smbuf[];
    __nv_bfloat16* Asm = smbuf;
    __nv_bfloat16* Bsm = smbuf + QC_AELEMS;

    const __nv_bfloat16 *AH, *AL, *BH, *BL;
    float* C; const float* bias;
    int rowBase, colBase;
    {
        int id = blockIdx.x;
        if (id < 128) {
            AH = g_encH; AL = g_encL; BH = g_WcTH; BL = g_WcTL;
            C = g_a2; bias = nullptr;
            colBase = (id & 3) * 128; rowBase = (id >> 2) * 128;
        } else {
            int j = id - 128;
            AH = g_decH; AL = g_decL; BH = g_WqTH; BL = g_WqTL;
            C = g_a1; bias = bq;
            colBase = (j & 3) * 128; rowBase = (j >> 2) * 128;
        }
    }

    const int tid = threadIdx.x, wid = tid >> 5, lane = tid & 31;
    const int warpM = wid & 3, warpN = wid >> 2;

    // loader indices: 512 (row, kcol8) units per matrix per precision; 2 per thread
    const int r0 = tid >> 2,         kc0 = (tid & 3) * 8;
    const int r1 = (tid + 256) >> 2, kc1 = kc0;            // (tid+256)&3 == tid&3

    const uint32_t sA = smem_to_u32(Asm);
    const uint32_t sB = smem_to_u32(Bsm);

    float acc[2][8][4];
    #pragma unroll
    for (int mi = 0; mi < 2; mi++)
        #pragma unroll
        for (int nf = 0; nf < 8; nf++)
            #pragma unroll
            for (int q = 0; q < 4; q++) acc[mi][nf][q] = 0.0f;

    uint4 va[4], vb[4];
    auto gload = [&](int ck){
        long a0 = (long)(rowBase + r0)*H_ + ck*32 + kc0;
        long a1 = (long)(rowBase + r1)*H_ + ck*32 + kc1;
        long b0 = (long)(colBase + r0)*H_ + ck*32 + kc0;
        long b1 = (long)(colBase + r1)*H_ + ck*32 + kc1;
        va[0] = *(const uint4*)(AH + a0); va[1] = *(const uint4*)(AH + a1);
        va[2] = *(const uint4*)(AL + a0); va[3] = *(const uint4*)(AL + a1);
        vb[0] = *(const uint4*)(BH + b0); vb[1] = *(const uint4*)(BH + b1);
        vb[2] = *(const uint4*)(BL + b0); vb[3] = *(const uint4*)(BL + b1);
    };
    auto sstore = [&](int buf){
        *(uint4*)(Asm + ((buf*2+0)*128 + r0)*QC_PAD + kc0) = va[0];
        *(uint4*)(Asm + ((buf*2+0)*128 + r1)*QC_PAD + kc1) = va[1];
        *(uint4*)(Asm + ((buf*2+1)*128 + r0)*QC_PAD + kc0) = va[2];
        *(uint4*)(Asm + ((buf*2+1)*128 + r1)*QC_PAD + kc1) = va[3];
        *(uint4*)(Bsm + ((buf*2+0)*128 + r0)*QC_PAD + kc0) = vb[0];
        *(uint4*)(Bsm + ((buf*2+0)*128 + r1)*QC_PAD + kc1) = vb[1];
        *(uint4*)(Bsm + ((buf*2+1)*128 + r0)*QC_PAD + kc0) = vb[2];
        *(uint4*)(Bsm + ((buf*2+1)*128 + r1)*QC_PAD + kc1) = vb[3];
    };

    gload(0);
    sstore(0);
    __syncthreads();

    // ldmatrix per-lane row/col components
    const int aRowL = lane & 15;                       // + mfrag base
    const int aColL = (lane >> 4) << 3;                // 0 or 8 (k within 16)
    const int bRowL = (lane & 7) | ((lane & 16) >> 1); // n within 16
    const int bColL = lane & 8;                        // 0 or 8 (k within 16)

    for (int ck = 0; ck < 16; ck++) {
        const int buf = ck & 1;
        if (ck < 15) gload(ck + 1);

        #pragma unroll
        for (int kk = 0; kk < 32; kk += 16) {
            uint32_t ah[2][4], al[2][4], bh[4][4], bl[4][4];
            #pragma unroll
            for (int mi = 0; mi < 2; mi++) {
                int row = warpM*32 + mi*16 + aRowL;
                int col = kk + aColL;
                LDSM4(ah[mi], sA + (uint32_t)((((buf*2+0)*128 + row)*QC_PAD + col)*2));
                LDSM4(al[mi], sA + (uint32_t)((((buf*2+1)*128 + row)*QC_PAD + col)*2));
            }
            #pragma unroll
            for (int bj = 0; bj < 4; bj++) {
                int n   = warpN*64 + bj*16 + bRowL;
                int col = kk + bColL;
                LDSM4(bh[bj], sB + (uint32_t)((((buf*2+0)*128 + n)*QC_PAD + col)*2));
                LDSM4(bl[bj], sB + (uint32_t)((((buf*2+1)*128 + n)*QC_PAD + col)*2));
            }
            #pragma unroll
            for (int mi = 0; mi < 2; mi++)
                #pragma unroll
                for (int bj = 0; bj < 4; bj++) {
                    MMA_BF16(acc[mi][2*bj],   ah[mi], bh[bj][0], bh[bj][1]);
                    MMA_BF16(acc[mi][2*bj],   ah[mi], bl[bj][0], bl[bj][1]);
                    MMA_BF16(acc[mi][2*bj],   al[mi], bh[bj][0], bh[bj][1]);
                    MMA_BF16(acc[mi][2*bj+1], ah[mi], bh[bj][2], bh[bj][3]);
                    MMA_BF16(acc[mi][2*bj+1], ah[mi], bl[bj][2], bl[bj][3]);
                    MMA_BF16(acc[mi][2*bj+1], al[mi], bh[bj][2], bh[bj][3]);
                }
        }

        if (ck < 15) sstore(buf ^ 1);
        __syncthreads();
    }

    // epilogue: D fragment -> gmem (float2 stores)
    #pragma unroll
    for (int mi = 0; mi < 2; mi++) {
        int row = rowBase + warpM*32 + mi*16 + (lane >> 2);
        #pragma unroll
        for (int nf = 0; nf < 8; nf++) {
            int col = colBase + warpN*64 + nf*8 + (lane & 3)*2;
            float d0 = acc[mi][nf][0], d1 = acc[mi][nf][1];
            float d2 = acc[mi][nf][2], d3 = acc[mi][nf][3];
            if (bias) {
                float2 bb = *(const float2*)(bias + col);
                d0 += bb.x; d1 += bb.y; d2 += bb.x; d3 += bb.y;
            }
            *(float2*)(C + (long)row*H_ + col)     = make_float2(d0, d1);
            *(float2*)(C + (long)(row+8)*H_ + col) = make_float2(d2, d3);
        }
    }
}

// -------- 64x64 split-K tile, double-buffered, f32x2 --------
template<int KCHUNK, bool SUMC>
__device__ __forceinline__ void tile64_body(
    const float* __restrict__ A, long ldaRow,
    const float* __restrict__ Bm,
    float* __restrict__ C, long ldcRow)
{
    __shared__ float As[2][16][64];
    __shared__ float Bs[2][16][64];

    const int tid = threadIdx.x;
    const int tx = tid & 15, ty = tid >> 4;
    const int aRow = tid >> 2, aCol = (tid & 3) << 2;
    const int bRow = tid >> 4, bCol = (tid & 15) << 2;

    uint64_t acc[4][2];
    #pragma unroll
    for (int i = 0; i < 4; i++) { acc[i][0] = 0ull; acc[i][1] = 0ull; }

    auto loadA = [&](int k0) -> float4 {
        const float* p = A + (long)aRow*ldaRow + k0 + aCol;
        float4 v = *(const float4*)p;
        if (SUMC) {
            float4 v1 = *(const float4*)(p + (long)TBH);
            float4 v2 = *(const float4*)(p + 2*(long)TBH);
            float4 v3 = *(const float4*)(p + 3*(long)TBH);
            v.x += v1.x + v2.x + v3.x; v.y += v1.y + v2.y + v3.y;
            v.z += v1.z + v2.z + v3.z; v.w += v1.w + v2.w + v3.w;
        }
        return v;
    };

    float4 av = loadA(0);
    float4 bv = *(const float4*)(Bm + (long)bRow*H_ + bCol);
    int buf = 0;

    for (int k0 = 0; k0 < KCHUNK; k0 += 16) {
        As[buf][aCol+0][aRow] = av.x;
        As[buf][aCol+1][aRow] = av.y;
        As[buf][aCol+2][aRow] = av.z;
        As[buf][aCol+3][aRow] = av.w;
        *(float4*)(&Bs[buf][bRow][bCol]) = bv;
        __syncthreads();

        if (k0 + 16 < KCHUNK) {
            av = loadA(k0 + 16);
            bv = *(const float4*)(Bm + (long)(k0 + 16 + bRow)*H_ + bCol);
        }

        #pragma unroll
        for (int k = 0; k < 16; k++) {
            float4 a = *(const float4*)(&As[buf][k][ty << 2]);
            ulonglong2 bb = *(const ulonglong2*)(&Bs[buf][k][tx << 2]);
            uint64_t pr[4] = {pk2dup(a.x), pk2dup(a.y), pk2dup(a.z), pk2dup(a.w)};
            #pragma unroll
            for (int i = 0; i < 4; i++) {
                ffma2(acc[i][0], pr[i], bb.x);
                ffma2(acc[i][1], pr[i], bb.y);
            }
        }
        __syncthreads();
        buf ^= 1;
    }

    #pragma unroll
    for (int i = 0; i < 4; i++) {
        float2 p0 = upk2(acc[i][0]);
        float2 p1 = upk2(acc[i][1]);
        float4 o = make_float4(p0.x, p0.y, p1.x, p1.y);
        *(float4*)(C + (long)((ty << 2) + i)*ldcRow + (tx << 2)) = o;
    }
}

__global__ __launch_bounds__(256)
void c_splitk_kernel(const float* __restrict__ align)
{
    const int nT = blockIdx.x, b = blockIdx.y, kz = blockIdx.z;
    const float* A  = align + (long)b*S_ + kz*128;
    const float* Bm = g_enc + ((long)b*S_ + kz*128)*H_ + nT*64;
    float* C = g_cp[kz] + (long)b*H_ + nT*64;
    tile64_body<128, false>(A, (long)B_*S_, Bm, C, (long)B_*H_);
}

__global__ __launch_bounds__(256)
void out_splitk_c_kernel(const float* __restrict__ Wo)
{
    const int nT = blockIdx.x, mT = blockIdx.y, kz = blockIdx.z;   // {0,1}
    const float* A  = g_cp[0] + kz*256 + (long)mT*64*H_;
    const float* Bm = Wo + (long)(kz*256)*H_ + nT*64;
    float* C = g_op[kz] + (long)mT*64*H_ + nT*64;
    tile64_body<256, true>(A, (long)H_, Bm, C, (long)H_);
}

__global__ __launch_bounds__(256)
void out_splitk_d_kernel(const float* __restrict__ dec, const float* __restrict__ Wo)
{
    const int nT = blockIdx.x, mT = blockIdx.y, kz = blockIdx.z + 2;
    const float* A  = dec + (kz-2)*256 + (long)mT*64*H_;
    const float* Bm = Wo + (long)(kz*256)*H_ + nT*64;
    float* C = g_op[kz] + (long)mT*64*H_ + nT*64;
    tile64_body<256, false>(A, (long)H_, Bm, C, (long)H_);
}

__global__ void out_reduce_kernel(float* __restrict__ attn_h,
                                  const float* __restrict__ bo)
{
    int idx = (blockIdx.x * 256 + threadIdx.x) * 4;
    int hq = idx & (H_-1);
    float4 a = *(const float4*)(&g_op[0][idx]);
    float4 b = *(const float4*)(&g_op[1][idx]);
    float4 c = *(const float4*)(&g_op[2][idx]);
    float4 d = *(const float4*)(&g_op[3][idx]);
    float4 bb = *(const float4*)(bo + hq);
    float4 o = make_float4(a.x+b.x+c.x+d.x+bb.x, a.y+b.y+c.y+d.y+bb.y,
                           a.z+b.z+c.z+d.z+bb.z, a.w+b.w+c.w+d.w+bb.w);
    *(float4*)(attn_h + idx) = o;
}

// -------- scores + softmax, 4 t-rows per block, prefetched s-tiles --------
__global__ __launch_bounds__(512)
void scores_softmax_kernel(const float* __restrict__ v,
                           float* __restrict__ align_out)
{
    const int tg = blockIdx.x;
    const int b  = blockIdx.y;
    const int tid = threadIdx.x;
    const int warp = tid >> 5, lane = tid & 31;

    __shared__ float sa1[4][H_];
    __shared__ float ssc[4][S_];
    __shared__ float sred[17];

    #pragma unroll
    for (int i = 0; i < 4; i++)
        sa1[i][tid] = g_a1[((tg*4 + i)*B_ + b)*H_ + tid];

    float4 v0 = *(const float4*)(v + lane*4);
    float4 v1 = *(const float4*)(v + lane*4 + 128);
    float4 v2 = *(const float4*)(v + lane*4 + 256);
    float4 v3 = *(const float4*)(v + lane*4 + 384);
    __syncthreads();

    const float* a2base = g_a2 + (long)b*S_*H_ + lane*4;

    float4 x[4];
    {
        const float* p = a2base + (long)warp*H_;
        x[0] = *(const float4*)(p);
        x[1] = *(const float4*)(p + 128);
        x[2] = *(const float4*)(p + 256);
        x[3] = *(const float4*)(p + 384);
    }

    for (int s = warp; s < S_; s += 16) {
        float4 y[4];
        const int sn = s + 16;
        if (sn < S_) {
            const float* p = a2base + (long)sn*H_;
            y[0] = *(const float4*)(p);
            y[1] = *(const float4*)(p + 128);
            y[2] = *(const float4*)(p + 256);
            y[3] = *(const float4*)(p + 384);
        }

        #pragma unroll
        for (int i = 0; i < 4; i++) {
            float4 a0 = *(const float4*)(&sa1[i][lane*4]);
            float4 a1 = *(const float4*)(&sa1[i][lane*4 + 128]);
            float4 a2 = *(const float4*)(&sa1[i][lane*4 + 256]);
            float4 a3 = *(const float4*)(&sa1[i][lane*4 + 384]);
            float acc = 0.0f;
            acc = fmaf(tanhf_hw(a0.x + x[0].x), v0.x, acc);
            acc = fmaf(tanhf_hw(a0.y + x[0].y), v0.y, acc);
            acc = fmaf(tanhf_hw(a0.z + x[0].z), v0.z, acc);
            acc = fmaf(tanhf_hw(a0.w + x[0].w), v0.w, acc);
            acc = fmaf(tanhf_hw(a1.x + x[1].x), v1.x, acc);
            acc = fmaf(tanhf_hw(a1.y + x[1].y), v1.y, acc);
            acc = fmaf(tanhf_hw(a1.z + x[1].z), v1.z, acc);
            acc = fmaf(tanhf_hw(a1.w + x[1].w), v1.w, acc);
            acc = fmaf(tanhf_hw(a2.x + x[2].x), v2.x, acc);
            acc = fmaf(tanhf_hw(a2.y + x[2].y), v2.y, acc);
            acc = fmaf(tanhf_hw(a2.z + x[2].z), v2.z, acc);
            acc = fmaf(tanhf_hw(a2.w + x[2].w), v2.w, acc);
            acc = fmaf(tanhf_hw(a3.x + x[3].x), v3.x, acc);
            acc = fmaf(tanhf_hw(a3.y + x[3].y), v3.y, acc);
            acc = fmaf(tanhf_hw(a3.z + x[3].z), v3.z, acc);
            acc = fmaf(tanhf_hw(a3.w + x[3].w), v3.w, acc);
            #pragma unroll
            for (int o = 16; o > 0; o >>= 1)
                acc += __shfl_xor_sync(0xffffffffu, acc, o);
            if (lane == 0) ssc[i][s] = acc;
        }
        x[0] = y[0]; x[1] = y[1]; x[2] = y[2]; x[3] = y[3];
    }
    __syncthreads();

    #pragma unroll
    for (int i = 0; i < 4; i++) {
        float xx = ssc[i][tid];
        float m = xx;
        #pragma unroll
        for (int o = 16; o > 0; o >>= 1) m = fmaxf(m, __shfl_xor_sync(0xffffffffu, m, o));
        if (lane == 0) sred[warp] = m;
        __syncthreads();
        if (warp == 0) {
            float mm = (lane < 16) ? sred[lane] : -1e30f;
            #pragma unroll
            for (int o = 8; o > 0; o >>= 1) mm = fmaxf(mm, __shfl_xor_sync(0xffffffffu, mm, o));
            if (lane == 0) sred[16] = mm;
        }
        __syncthreads();
        const float mx = sred[16];
        float e = ex2f_((xx - mx) * 1.4426950408889634f);
        float ssum = e;
        #pragma unroll
        for (int o = 16; o > 0; o >>= 1) ssum += __shfl_xor_sync(0xffffffffu, ssum, o);
        __syncthreads();
        if (lane == 0) sred[warp] = ssum;
        __syncthreads();
        if (warp == 0) {
            float t = (lane < 16) ? sred[lane] : 0.0f;
            #pragma unroll
            for (int o = 8; o > 0; o >>= 1) t += __shfl_xor_sync(0xffffffffu, t, o);
            if (lane == 0) sred[16] = t;
        }
        __syncthreads();
        float p = e * rcpf_(sred[16]);
        align_out[(long)((tg*4 + i)*B_ + b)*S_ + tid] = p;
        __syncthreads();
    }
}

extern "C" void kernel_launch(void* const* d_in, const int* in_sizes, int n_in,
                              void* d_out, int out_size)
{
    const float* dec  = (const float*)d_in[0];
    const float* enc  = (const float*)d_in[1];
    const float* cov  = (const float*)d_in[2];
    const float* Wq   = (const float*)d_in[3];
    const float* bq   = (const float*)d_in[4];
    const float* Wc   = (const float*)d_in[5];
    const float* v    = (const float*)d_in[6];
    const float* Wo   = (const float*)d_in[7];
    const float* bo   = (const float*)d_in[8];
    const float* wcov = (const float*)d_in[9];

    float* attn_h = (float*)d_out;
    float* align  = (float*)d_out + TBH;

    static cudaStream_t s1 = nullptr;
    static cudaEvent_t evFork = nullptr, evW = nullptr, evJoin = nullptr;
    if (!s1) {
        cudaStreamCreateWithFlags(&s1, cudaStreamNonBlocking);
        cudaEventCreateWithFlags(&evFork, cudaEventDisableTiming);
        cudaEventCreateWithFlags(&evW, cudaEventDisableTiming);
        cudaEventCreateWithFlags(&evJoin, cudaEventDisableTiming);
        cudaFuncSetAttribute(qc_hmma_kernel,
                             cudaFuncAttributeMaxDynamicSharedMemorySize, QC_SMEM_BYTES);
    }

    // Fork: weight transposes + dec split + out_d on side stream.
    cudaEventRecord(evFork, 0);
    cudaStreamWaitEvent(s1, evFork, 0);
    transW_kernel<<<dim3(16, 16, 2), dim3(32, 8), 0, s1>>>(Wq, Wc);
    split_dec_kernel<<<TBH/256, 256, 0, s1>>>(dec);
    cudaEventRecord(evW, s1);
    out_splitk_d_kernel<<<dim3(8, 8, 2), 256, 0, s1>>>(dec, Wo);
    cudaEventRecord(evJoin, s1);

    // Main chain.
    prep_enc_kernel<<<BSH/256, 256>>>(enc, cov, wcov);
    cudaStreamWaitEvent(0, evW, 0);
    qc_hmma_kernel<<<144, 256, QC_SMEM_BYTES>>>(bq);
    scores_softmax_kernel<<<dim3(16, 8), 512>>>(v, align);
    c_splitk_kernel<<<dim3(8, 8, 4), 256>>>(align);
    out_splitk_c_kernel<<<dim3(8, 8, 2), 256>>>(Wo);

    cudaStreamWaitEvent(0, evJoin, 0);
    out_reduce_kernel<<<TBH/1024, 256>>>(attn_h, bo);
}